// round 1
// baseline (speedup 1.0000x reference)
#include <cuda_runtime.h>
#include <cuda_bf16.h>

// Sampler_51419348468365
//
// Reference epilogue is: out = stop_gradient(1 - y) + y, which value-wise is
// (1 - y) + y == 1.0 up to <= ~1.2e-7 relative fp32 rounding (y = softmax in
// (0,1)). Bench tolerance is 1e-3, so the correct (and fastest) kernel writes
// the constant 1.0f to all out_size elements. Pure HBM-store kernel,
// vectorized as float4.

__global__ void Sampler_51419348468365_fill_ones(float4* __restrict__ out4,
                                                 int n4,
                                                 float* __restrict__ out_tail,
                                                 int n_total) {
    const float4 ones = make_float4(1.0f, 1.0f, 1.0f, 1.0f);
    int stride = gridDim.x * blockDim.x;
    for (int i = blockIdx.x * blockDim.x + threadIdx.x; i < n4; i += stride) {
        out4[i] = ones;
    }
    // Tail (out_size not divisible by 4) — handled by thread 0 of block 0.
    if (blockIdx.x == 0 && threadIdx.x == 0) {
        for (int i = n4 * 4; i < n_total; ++i) out_tail[i] = 1.0f;
    }
}

extern "C" void kernel_launch(void* const* d_in, const int* in_sizes, int n_in,
                              void* d_out, int out_size) {
    (void)d_in; (void)in_sizes; (void)n_in;
    float* out = (float*)d_out;
    int n4 = out_size / 4;  // 262144 for out_size = 1048576
    int threads = 256;
    int blocks = (n4 + threads - 1) / threads;
    if (blocks > 8192) blocks = 8192;
    if (blocks < 1) blocks = 1;
    Sampler_51419348468365_fill_ones<<<blocks, threads>>>(
        (float4*)out, n4, out, out_size);
}

// round 2
// speedup vs baseline: 1.0350x; 1.0350x over previous
#include <cuda_runtime.h>
#include <cuda_bf16.h>

// Sampler_51419348468365
//
// out = stop_gradient(1 - y) + y  ==  1.0f value-wise (y = softmax in (0,1),
// fp32 rounding error <= ~1.2e-7, tolerance 1e-3). Kernel writes constant 1.0f.
//
// R1: minimal-instruction variant. One STG.128 per thread, no grid-stride
// loop, no per-thread tail scan. Tail (out_size % 4) handled by <=3 scalar
// stores from threads of the last block (dead code for out_size = 2^20).

__global__ __launch_bounds__(256, 1)
void Sampler_fill_ones(float4* __restrict__ out4, int n4,
                       float* __restrict__ out_tail, int n_total) {
    int i = blockIdx.x * 256 + threadIdx.x;
    const float4 ones = make_float4(1.0f, 1.0f, 1.0f, 1.0f);
    if (i < n4) {
        out4[i] = ones;
    }
    // Tail: first (n_total - 4*n4) threads past the end write scalars.
    int t = i - n4;               // >= 0 only for trailing threads
    if (t >= 0 && 4 * n4 + t < n_total) {
        out_tail[4 * n4 + t] = 1.0f;
    }
}

extern "C" void kernel_launch(void* const* d_in, const int* in_sizes, int n_in,
                              void* d_out, int out_size) {
    (void)d_in; (void)in_sizes; (void)n_in;
    float* out = (float*)d_out;
    int n4 = out_size / 4;                     // 262144
    int total_threads = n4 + (out_size - 4 * n4);  // vector threads + tail threads
    if (total_threads < 1) total_threads = 1;
    int blocks = (total_threads + 255) / 256;  // 1024 blocks for 2^20 elements
    Sampler_fill_ones<<<blocks, 256>>>((float4*)out, n4, out, out_size);
}